// round 2
// baseline (speedup 1.0000x reference)
#include <cuda_runtime.h>
#include <cuda_bf16.h>
#include <cstdint>

#define NN   100000
#define NE   1250000
#define IND  64
#define HID  128
#define OUTD 64

// ---------------- device scratch (no cudaMalloc allowed) ----------------
__device__ __align__(16) float g_agg[NN * IND];   // 25.6 MB
__device__ float g_deg[NN];
__device__ __align__(16) __nv_bfloat16 g_Whi[57344];  // W1..W4 transposed [n][k], bf16 hi
__device__ __align__(16) __nv_bfloat16 g_Wlo[57344];  // bf16 residual
__device__ int g_is64;

// ---------------- helpers ----------------
__device__ __forceinline__ void mma16816(float* c,
        uint32_t a0, uint32_t a1, uint32_t a2, uint32_t a3,
        uint32_t b0, uint32_t b1) {
    asm volatile(
        "mma.sync.aligned.m16n8k16.row.col.f32.bf16.bf16.f32 "
        "{%0,%1,%2,%3}, {%4,%5,%6,%7}, {%8,%9}, {%0,%1,%2,%3};"
        : "+f"(c[0]), "+f"(c[1]), "+f"(c[2]), "+f"(c[3])
        : "r"(a0), "r"(a1), "r"(a2), "r"(a3), "r"(b0), "r"(b1));
}

// split two f32 into packed bf16x2 hi + packed bf16x2 residual
__device__ __forceinline__ void split2(float x0, float x1, uint32_t& hi, uint32_t& lo) {
    __nv_bfloat162 h = __floats2bfloat162_rn(x0, x1);
    float r0 = x0 - __bfloat162float(h.x);
    float r1 = x1 - __bfloat162float(h.y);
    __nv_bfloat162 l = __floats2bfloat162_rn(r0, r1);
    hi = *reinterpret_cast<uint32_t*>(&h);
    lo = *reinterpret_cast<uint32_t*>(&l);
}

// ---------------- kernel 1: zero scratch ----------------
__global__ void zero_kernel() {
    int i = blockIdx.x * blockDim.x + threadIdx.x;
    int total = NN * IND + NN;
    if (i < NN * IND) g_agg[i] = 0.f;
    else if (i < total) g_deg[i - NN * IND] = 0.f;
}

// ---------------- kernel 2: detect edge_index dtype (int64 vs int32) --------
__global__ void detect_kernel(const unsigned int* words) {
    if (threadIdx.x == 0 && blockIdx.x == 0) {
        int is64 = 1;
        for (int t = 0; t < 256; t++)
            if (words[2 * t + 1] != 0u) { is64 = 0; break; }
        g_is64 = is64;
    }
}

// ---------------- kernel 3: edge scatter via vector red ---------------------
// 16 threads per edge, each does one red.global.add.v4.f32 (16B).
__global__ void scatter_kernel(const void* ei_raw, const float* __restrict__ x) {
    long long t = (long long)blockIdx.x * 256 + threadIdx.x;
    long long e = t >> 4;
    if (e >= NE) return;
    int chunk = (int)(t & 15);
    int r, c;
    if (g_is64) {
        const long long* ei = (const long long*)ei_raw;
        r = (int)ei[e]; c = (int)ei[NE + e];
    } else {
        const int* ei = (const int*)ei_raw;
        r = ei[e]; c = ei[NE + e];
    }
    float4 v = *(const float4*)(x + (size_t)c * IND + chunk * 4);
    float* dst = g_agg + (size_t)r * IND + chunk * 4;
    asm volatile("red.global.add.v4.f32 [%0], {%1,%2,%3,%4};"
                 :: "l"(dst), "f"(v.x), "f"(v.y), "f"(v.z), "f"(v.w) : "memory");
    if (chunk == 0)
        asm volatile("red.global.add.f32 [%0], %1;"
                     :: "l"(g_deg + r), "f"(1.0f) : "memory");
}

// ---------------- kernel 4: weight transpose + bf16 hi/lo split -------------
__global__ void wprep_kernel(const float* __restrict__ W1, const float* __restrict__ W2,
                             const float* __restrict__ W3, const float* __restrict__ W4) {
    int idx = blockIdx.x * 256 + threadIdx.x;
    if (idx >= 57344) return;
    float v;
    if (idx < 16384)       { int j = idx;         int n = j >> 7, k = j & 127; v = W1[k * HID + n]; }
    else if (idx < 32768)  { int j = idx - 16384; int n = j >> 7, k = j & 127; v = W2[k * HID + n]; }
    else if (idx < 49152)  { int j = idx - 32768; int n = j >> 7, k = j & 127; v = W3[k * HID + n]; }
    else                   { int j = idx - 49152; int n = j >> 7, k = j & 127; v = W4[k * OUTD + n]; }
    __nv_bfloat16 hi = __float2bfloat16(v);
    g_Whi[idx] = hi;
    g_Wlo[idx] = __float2bfloat16(v - __bfloat162float(hi));
}

// ---------------- kernel 5: fused 4-layer MLP on mma.sync bf16 --------------
// CTA = 256 threads (8 warps), 128 node-rows per CTA, 16 rows per warp.
// Activations live in registers across all layers (C-frag == next A-frag layout).
// smem: W hi [128][136] + W lo [128][136] bf16 + bias[128] f32 = 70144 B.
#define WPAD 136
#define SM_WHI_OFF 0
#define SM_WLO_OFF 34816
#define SM_BIAS_OFF 69632
#define SM_TOTAL 70144

__global__ void __launch_bounds__(256, 1)
mlp_kernel(const float* __restrict__ x,
           const float* __restrict__ b1, const float* __restrict__ b2,
           const float* __restrict__ b3, const float* __restrict__ b4,
           float* __restrict__ out) {
    extern __shared__ char sm[];
    __nv_bfloat16* sWhi = (__nv_bfloat16*)(sm + SM_WHI_OFF);
    __nv_bfloat16* sWlo = (__nv_bfloat16*)(sm + SM_WLO_OFF);
    float* sbias = (float*)(sm + SM_BIAS_OFF);

    int tid = threadIdx.x;
    int wid = tid >> 5, lane = tid & 31;
    int gid = lane >> 2, tig = lane & 3;
    int base = blockIdx.x * 128;
    int r0 = base + wid * 16 + gid;
    int r8 = r0 + 8;
    bool v0 = r0 < NN, v8 = r8 < NN;

    uint32_t ahi[32], alo[32];

    // ---- build layer-1 A fragments from x | agg/deg ----
    float inv0 = v0 ? (1.0f / fmaxf(g_deg[r0], 1.0f)) : 0.f;
    float inv8 = v8 ? (1.0f / fmaxf(g_deg[r8], 1.0f)) : 0.f;
    #pragma unroll
    for (int kk = 0; kk < 8; kk++) {
        #pragma unroll
        for (int h = 0; h < 4; h++) {
            int  rr  = (h & 1) ? r8 : r0;
            bool vv  = (h & 1) ? v8 : v0;
            float iv = (h & 1) ? inv8 : inv0;
            int c = kk * 16 + ((h & 2) ? 8 : 0) + tig * 2;
            float x0 = 0.f, x1 = 0.f;
            if (vv) {
                if (c < 64) {
                    float2 t = *(const float2*)(x + (size_t)rr * IND + c);
                    x0 = t.x; x1 = t.y;
                } else {
                    float2 t = *(const float2*)(g_agg + (size_t)rr * IND + (c - 64));
                    x0 = t.x * iv; x1 = t.y * iv;
                }
            }
            split2(x0, x1, ahi[kk * 4 + h], alo[kk * 4 + h]);
        }
    }

    // ---- hidden layers 1-3 (128 -> 128) ----
    const float* bptr[3] = { b1, b2, b3 };
    for (int l = 0; l < 3; l++) {
        __syncthreads();
        const uint4* ghi = (const uint4*)(g_Whi + l * 16384);
        const uint4* glo = (const uint4*)(g_Wlo + l * 16384);
        for (int i = tid; i < 2048; i += 256) {
            int n = i >> 4, c8 = (i & 15) << 3;
            *(uint4*)(sWhi + n * WPAD + c8) = ghi[i];
            *(uint4*)(sWlo + n * WPAD + c8) = glo[i];
        }
        if (tid < 128) sbias[tid] = bptr[l][tid];
        __syncthreads();

        float acc[64];
        #pragma unroll
        for (int nt = 0; nt < 16; nt++) {
            float2 bb = *(const float2*)(sbias + nt * 8 + tig * 2);
            acc[nt * 4 + 0] = bb.x; acc[nt * 4 + 1] = bb.y;
            acc[nt * 4 + 2] = bb.x; acc[nt * 4 + 3] = bb.y;
        }
        #pragma unroll
        for (int kk = 0; kk < 8; kk++) {
            #pragma unroll
            for (int nt = 0; nt < 16; nt++) {
                int n = nt * 8 + gid;
                uint32_t bh0 = *(const uint32_t*)(sWhi + n * WPAD + kk * 16 + tig * 2);
                uint32_t bh1 = *(const uint32_t*)(sWhi + n * WPAD + kk * 16 + 8 + tig * 2);
                uint32_t bl0 = *(const uint32_t*)(sWlo + n * WPAD + kk * 16 + tig * 2);
                uint32_t bl1 = *(const uint32_t*)(sWlo + n * WPAD + kk * 16 + 8 + tig * 2);
                mma16816(&acc[nt * 4], ahi[kk*4], ahi[kk*4+1], ahi[kk*4+2], ahi[kk*4+3], bh0, bh1);
                mma16816(&acc[nt * 4], ahi[kk*4], ahi[kk*4+1], ahi[kk*4+2], ahi[kk*4+3], bl0, bl1);
                mma16816(&acc[nt * 4], alo[kk*4], alo[kk*4+1], alo[kk*4+2], alo[kk*4+3], bh0, bh1);
            }
        }
        // ReLU + re-split into next layer's A fragments (pure register shuffle)
        #pragma unroll
        for (int kk = 0; kk < 8; kk++) {
            float p0 = fmaxf(acc[8*kk + 0], 0.f), p1 = fmaxf(acc[8*kk + 1], 0.f);
            split2(p0, p1, ahi[4*kk + 0], alo[4*kk + 0]);
            float p2 = fmaxf(acc[8*kk + 2], 0.f), p3 = fmaxf(acc[8*kk + 3], 0.f);
            split2(p2, p3, ahi[4*kk + 1], alo[4*kk + 1]);
            float p4 = fmaxf(acc[8*kk + 4], 0.f), p5 = fmaxf(acc[8*kk + 5], 0.f);
            split2(p4, p5, ahi[4*kk + 2], alo[4*kk + 2]);
            float p6 = fmaxf(acc[8*kk + 6], 0.f), p7 = fmaxf(acc[8*kk + 7], 0.f);
            split2(p6, p7, ahi[4*kk + 3], alo[4*kk + 3]);
        }
    }

    // ---- layer 4 (128 -> 64) + store ----
    __syncthreads();
    {
        const uint4* ghi = (const uint4*)(g_Whi + 49152);
        const uint4* glo = (const uint4*)(g_Wlo + 49152);
        for (int i = tid; i < 1024; i += 256) {
            int n = i >> 4, c8 = (i & 15) << 3;
            *(uint4*)(sWhi + n * WPAD + c8) = ghi[i];
            *(uint4*)(sWlo + n * WPAD + c8) = glo[i];
        }
        if (tid < 64) sbias[tid] = b4[tid];
    }
    __syncthreads();

    float acc4[32];
    #pragma unroll
    for (int nt = 0; nt < 8; nt++) {
        float2 bb = *(const float2*)(sbias + nt * 8 + tig * 2);
        acc4[nt * 4 + 0] = bb.x; acc4[nt * 4 + 1] = bb.y;
        acc4[nt * 4 + 2] = bb.x; acc4[nt * 4 + 3] = bb.y;
    }
    #pragma unroll
    for (int kk = 0; kk < 8; kk++) {
        #pragma unroll
        for (int nt = 0; nt < 8; nt++) {
            int n = nt * 8 + gid;
            uint32_t bh0 = *(const uint32_t*)(sWhi + n * WPAD + kk * 16 + tig * 2);
            uint32_t bh1 = *(const uint32_t*)(sWhi + n * WPAD + kk * 16 + 8 + tig * 2);
            uint32_t bl0 = *(const uint32_t*)(sWlo + n * WPAD + kk * 16 + tig * 2);
            uint32_t bl1 = *(const uint32_t*)(sWlo + n * WPAD + kk * 16 + 8 + tig * 2);
            mma16816(&acc4[nt * 4], ahi[kk*4], ahi[kk*4+1], ahi[kk*4+2], ahi[kk*4+3], bh0, bh1);
            mma16816(&acc4[nt * 4], ahi[kk*4], ahi[kk*4+1], ahi[kk*4+2], ahi[kk*4+3], bl0, bl1);
            mma16816(&acc4[nt * 4], alo[kk*4], alo[kk*4+1], alo[kk*4+2], alo[kk*4+3], bh0, bh1);
        }
    }
    #pragma unroll
    for (int nt = 0; nt < 8; nt++) {
        int col = nt * 8 + tig * 2;
        if (v0) {
            float2 o; o.x = acc4[nt*4 + 0]; o.y = acc4[nt*4 + 1];
            *(float2*)(out + (size_t)r0 * OUTD + col) = o;
        }
        if (v8) {
            float2 o; o.x = acc4[nt*4 + 2]; o.y = acc4[nt*4 + 3];
            *(float2*)(out + (size_t)r8 * OUTD + col) = o;
        }
    }
}

// ---------------- launch ----------------
extern "C" void kernel_launch(void* const* d_in, const int* in_sizes, int n_in,
                              void* d_out, int out_size) {
    const float* x  = (const float*)d_in[0];
    const void*  ei = d_in[1];
    const float* W1 = (const float*)d_in[2];
    const float* b1 = (const float*)d_in[3];
    const float* W2 = (const float*)d_in[4];
    const float* b2 = (const float*)d_in[5];
    const float* W3 = (const float*)d_in[6];
    const float* b3 = (const float*)d_in[7];
    const float* W4 = (const float*)d_in[8];
    const float* b4 = (const float*)d_in[9];
    float* out = (float*)d_out;

    zero_kernel<<<(NN * IND + NN + 255) / 256, 256>>>();
    detect_kernel<<<1, 32>>>((const unsigned int*)ei);
    scatter_kernel<<<(int)(((long long)NE * 16 + 255) / 256), 256>>>(ei, x);
    wprep_kernel<<<(57344 + 255) / 256, 256>>>(W1, W2, W3, W4);

    cudaFuncSetAttribute(mlp_kernel, cudaFuncAttributeMaxDynamicSharedMemorySize, SM_TOTAL);
    mlp_kernel<<<(NN + 127) / 128, 256, SM_TOTAL>>>(x, b1, b2, b3, b4, out);
}

// round 3
// speedup vs baseline: 1.1716x; 1.1716x over previous
#include <cuda_runtime.h>
#include <cuda_bf16.h>
#include <cstdint>

#define NN   100000
#define NE   1250000
#define IND  64
#define HID  128
#define OUTD 64

// ---------------- device scratch (no cudaMalloc allowed) ----------------
__device__ __align__(16) float g_agg[NN * IND];   // normalized mean-agg, 25.6 MB
__device__ int g_degi[NN];
__device__ int g_off[NN + 1];
__device__ int g_cursor[NN];
__device__ int g_bsum[128];
__device__ int g_ecol[NE];
__device__ __align__(16) __nv_bfloat16 g_Whi[57344];  // W1..W4 transposed [n][k], bf16 hi
__device__ __align__(16) __nv_bfloat16 g_Wlo[57344];  // bf16 residual
__device__ int g_is64;

// ---------------- helpers ----------------
__device__ __forceinline__ void mma16816(float* c,
        uint32_t a0, uint32_t a1, uint32_t a2, uint32_t a3,
        uint32_t b0, uint32_t b1) {
    asm volatile(
        "mma.sync.aligned.m16n8k16.row.col.f32.bf16.bf16.f32 "
        "{%0,%1,%2,%3}, {%4,%5,%6,%7}, {%8,%9}, {%0,%1,%2,%3};"
        : "+f"(c[0]), "+f"(c[1]), "+f"(c[2]), "+f"(c[3])
        : "r"(a0), "r"(a1), "r"(a2), "r"(a3), "r"(b0), "r"(b1));
}

__device__ __forceinline__ void split2(float x0, float x1, uint32_t& hi, uint32_t& lo) {
    __nv_bfloat162 h = __floats2bfloat162_rn(x0, x1);
    float r0 = x0 - __bfloat162float(h.x);
    float r1 = x1 - __bfloat162float(h.y);
    __nv_bfloat162 l = __floats2bfloat162_rn(r0, r1);
    hi = *reinterpret_cast<uint32_t*>(&h);
    lo = *reinterpret_cast<uint32_t*>(&l);
}

__device__ __forceinline__ void load_edge(const void* ei_raw, long long e, int& r, int& c) {
    if (g_is64) {
        const long long* ei = (const long long*)ei_raw;
        r = (int)ei[e]; c = (int)ei[NE + e];
    } else {
        const int* ei = (const int*)ei_raw;
        r = ei[e]; c = ei[NE + e];
    }
}

// ---------------- CSR build ----------------
__global__ void zero_deg_kernel() {
    int i = blockIdx.x * blockDim.x + threadIdx.x;
    if (i < NN) g_degi[i] = 0;
}

__global__ void detect_kernel(const unsigned int* words) {
    if (threadIdx.x == 0 && blockIdx.x == 0) {
        int is64 = 1;
        for (int t = 0; t < 256; t++)
            if (words[2 * t + 1] != 0u) { is64 = 0; break; }
        g_is64 = is64;
    }
}

__global__ void hist_kernel(const void* ei_raw) {
    long long e = (long long)blockIdx.x * 256 + threadIdx.x;
    if (e >= NE) return;
    int r, c;
    load_edge(ei_raw, e, r, c);
    asm volatile("red.global.add.u32 [%0], %1;" :: "l"(g_degi + r), "r"(1) : "memory");
}

// block-level exclusive scan (1024 threads/block)
__global__ void scan_block_kernel() {
    __shared__ int s[1024];
    int tid = threadIdx.x;
    int i = blockIdx.x * 1024 + tid;
    int val = (i < NN) ? g_degi[i] : 0;
    s[tid] = val;
    __syncthreads();
    #pragma unroll
    for (int d = 1; d < 1024; d <<= 1) {
        int t = (tid >= d) ? s[tid - d] : 0;
        __syncthreads();
        s[tid] += t;
        __syncthreads();
    }
    if (i < NN) g_off[i] = s[tid] - val;
    if (tid == 1023) g_bsum[blockIdx.x] = s[1023];
}

__global__ void scan_top_kernel(int nblocks) {
    if (threadIdx.x == 0) {
        int run = 0;
        for (int b = 0; b < nblocks; b++) { int t = g_bsum[b]; g_bsum[b] = run; run += t; }
    }
}

__global__ void scan_add_kernel() {
    int i = blockIdx.x * blockDim.x + threadIdx.x;
    if (i < NN) {
        int off = g_off[i] + g_bsum[i >> 10];
        g_off[i] = off;
        g_cursor[i] = off;
    }
    if (i == 0) g_off[NN] = NE;
}

__global__ void place_kernel(const void* ei_raw) {
    long long e = (long long)blockIdx.x * 256 + threadIdx.x;
    if (e >= NE) return;
    int r, c;
    load_edge(ei_raw, e, r, c);
    int pos = atomicAdd(&g_cursor[r], 1);
    g_ecol[pos] = c;
}

// ---------------- gather-sum (no float atomics) ----------------
// one warp per node; lane handles 2 feature dims (float2)
__global__ void __launch_bounds__(256)
gather_kernel(const float* __restrict__ x) {
    int node = blockIdx.x * 8 + (threadIdx.x >> 5);
    if (node >= NN) return;
    int lane = threadIdx.x & 31;
    int off0 = g_off[node], off1 = g_off[node + 1];
    int deg = off1 - off0;
    float ax = 0.f, ay = 0.f;
    for (int i = 0; i < deg; i += 32) {
        int col_l = (i + lane < deg) ? g_ecol[off0 + i + lane] : 0;
        int cnt = min(32, deg - i);
        for (int j = 0; j < cnt; j++) {
            int cc = __shfl_sync(0xFFFFFFFFu, col_l, j);
            float2 v = *(const float2*)(x + (size_t)cc * IND + lane * 2);
            ax += v.x; ay += v.y;
        }
    }
    float inv = 1.0f / fmaxf((float)deg, 1.0f);
    float2 o; o.x = ax * inv; o.y = ay * inv;
    *(float2*)(g_agg + (size_t)node * IND + lane * 2) = o;
}

// ---------------- weight transpose + bf16 hi/lo split -------------
__global__ void wprep_kernel(const float* __restrict__ W1, const float* __restrict__ W2,
                             const float* __restrict__ W3, const float* __restrict__ W4) {
    int idx = blockIdx.x * 256 + threadIdx.x;
    if (idx >= 57344) return;
    float v;
    if (idx < 16384)       { int j = idx;         int n = j >> 7, k = j & 127; v = W1[k * HID + n]; }
    else if (idx < 32768)  { int j = idx - 16384; int n = j >> 7, k = j & 127; v = W2[k * HID + n]; }
    else if (idx < 49152)  { int j = idx - 32768; int n = j >> 7, k = j & 127; v = W3[k * HID + n]; }
    else                   { int j = idx - 49152; int n = j >> 7, k = j & 127; v = W4[k * OUTD + n]; }
    __nv_bfloat16 hi = __float2bfloat16(v);
    g_Whi[idx] = hi;
    g_Wlo[idx] = __float2bfloat16(v - __bfloat162float(hi));
}

// ---------------- fused 4-layer MLP on mma.sync bf16 --------------
#define WPAD 136
#define SM_WHI_OFF 0
#define SM_WLO_OFF 34816
#define SM_BIAS_OFF 69632
#define SM_TOTAL 70144

__global__ void __launch_bounds__(256, 1)
mlp_kernel(const float* __restrict__ x,
           const float* __restrict__ b1, const float* __restrict__ b2,
           const float* __restrict__ b3, const float* __restrict__ b4,
           float* __restrict__ out) {
    extern __shared__ char sm[];
    __nv_bfloat16* sWhi = (__nv_bfloat16*)(sm + SM_WHI_OFF);
    __nv_bfloat16* sWlo = (__nv_bfloat16*)(sm + SM_WLO_OFF);
    float* sbias = (float*)(sm + SM_BIAS_OFF);

    int tid = threadIdx.x;
    int wid = tid >> 5, lane = tid & 31;
    int gid = lane >> 2, tig = lane & 3;
    int base = blockIdx.x * 128;
    int r0 = base + wid * 16 + gid;
    int r8 = r0 + 8;
    bool v0 = r0 < NN, v8 = r8 < NN;

    uint32_t ahi[32], alo[32];

    // ---- build layer-1 A fragments from x | agg (pre-normalized) ----
    #pragma unroll
    for (int kk = 0; kk < 8; kk++) {
        #pragma unroll
        for (int h = 0; h < 4; h++) {
            int  rr  = (h & 1) ? r8 : r0;
            bool vv  = (h & 1) ? v8 : v0;
            int c = kk * 16 + ((h & 2) ? 8 : 0) + tig * 2;
            float x0 = 0.f, x1 = 0.f;
            if (vv) {
                const float* src = (c < 64) ? (x + (size_t)rr * IND + c)
                                            : (g_agg + (size_t)rr * IND + (c - 64));
                float2 t = *(const float2*)src;
                x0 = t.x; x1 = t.y;
            }
            split2(x0, x1, ahi[kk * 4 + h], alo[kk * 4 + h]);
        }
    }

    // ---- hidden layers 1-3 (128 -> 128) ----
    const float* bptr[3] = { b1, b2, b3 };
    for (int l = 0; l < 3; l++) {
        __syncthreads();
        const uint4* ghi = (const uint4*)(g_Whi + l * 16384);
        const uint4* glo = (const uint4*)(g_Wlo + l * 16384);
        for (int i = tid; i < 2048; i += 256) {
            int n = i >> 4, c8 = (i & 15) << 3;
            *(uint4*)(sWhi + n * WPAD + c8) = ghi[i];
            *(uint4*)(sWlo + n * WPAD + c8) = glo[i];
        }
        if (tid < 128) sbias[tid] = bptr[l][tid];
        __syncthreads();

        float acc[64];
        #pragma unroll
        for (int nt = 0; nt < 16; nt++) {
            float2 bb = *(const float2*)(sbias + nt * 8 + tig * 2);
            acc[nt * 4 + 0] = bb.x; acc[nt * 4 + 1] = bb.y;
            acc[nt * 4 + 2] = bb.x; acc[nt * 4 + 3] = bb.y;
        }
        #pragma unroll
        for (int kk = 0; kk < 8; kk++) {
            #pragma unroll
            for (int nt = 0; nt < 16; nt++) {
                int n = nt * 8 + gid;
                uint32_t bh0 = *(const uint32_t*)(sWhi + n * WPAD + kk * 16 + tig * 2);
                uint32_t bh1 = *(const uint32_t*)(sWhi + n * WPAD + kk * 16 + 8 + tig * 2);
                uint32_t bl0 = *(const uint32_t*)(sWlo + n * WPAD + kk * 16 + tig * 2);
                uint32_t bl1 = *(const uint32_t*)(sWlo + n * WPAD + kk * 16 + 8 + tig * 2);
                mma16816(&acc[nt * 4], ahi[kk*4], ahi[kk*4+1], ahi[kk*4+2], ahi[kk*4+3], bh0, bh1);
                mma16816(&acc[nt * 4], ahi[kk*4], ahi[kk*4+1], ahi[kk*4+2], ahi[kk*4+3], bl0, bl1);
                mma16816(&acc[nt * 4], alo[kk*4], alo[kk*4+1], alo[kk*4+2], alo[kk*4+3], bh0, bh1);
            }
        }
        #pragma unroll
        for (int kk = 0; kk < 8; kk++) {
            float p0 = fmaxf(acc[8*kk + 0], 0.f), p1 = fmaxf(acc[8*kk + 1], 0.f);
            split2(p0, p1, ahi[4*kk + 0], alo[4*kk + 0]);
            float p2 = fmaxf(acc[8*kk + 2], 0.f), p3 = fmaxf(acc[8*kk + 3], 0.f);
            split2(p2, p3, ahi[4*kk + 1], alo[4*kk + 1]);
            float p4 = fmaxf(acc[8*kk + 4], 0.f), p5 = fmaxf(acc[8*kk + 5], 0.f);
            split2(p4, p5, ahi[4*kk + 2], alo[4*kk + 2]);
            float p6 = fmaxf(acc[8*kk + 6], 0.f), p7 = fmaxf(acc[8*kk + 7], 0.f);
            split2(p6, p7, ahi[4*kk + 3], alo[4*kk + 3]);
        }
    }

    // ---- layer 4 (128 -> 64) + store ----
    __syncthreads();
    {
        const uint4* ghi = (const uint4*)(g_Whi + 49152);
        const uint4* glo = (const uint4*)(g_Wlo + 49152);
        for (int i = tid; i < 1024; i += 256) {
            int n = i >> 4, c8 = (i & 15) << 3;
            *(uint4*)(sWhi + n * WPAD + c8) = ghi[i];
            *(uint4*)(sWlo + n * WPAD + c8) = glo[i];
        }
        if (tid < 64) sbias[tid] = b4[tid];
    }
    __syncthreads();

    float acc4[32];
    #pragma unroll
    for (int nt = 0; nt < 8; nt++) {
        float2 bb = *(const float2*)(sbias + nt * 8 + tig * 2);
        acc4[nt * 4 + 0] = bb.x; acc4[nt * 4 + 1] = bb.y;
        acc4[nt * 4 + 2] = bb.x; acc4[nt * 4 + 3] = bb.y;
    }
    #pragma unroll
    for (int kk = 0; kk < 8; kk++) {
        #pragma unroll
        for (int nt = 0; nt < 8; nt++) {
            int n = nt * 8 + gid;
            uint32_t bh0 = *(const uint32_t*)(sWhi + n * WPAD + kk * 16 + tig * 2);
            uint32_t bh1 = *(const uint32_t*)(sWhi + n * WPAD + kk * 16 + 8 + tig * 2);
            uint32_t bl0 = *(const uint32_t*)(sWlo + n * WPAD + kk * 16 + tig * 2);
            uint32_t bl1 = *(const uint32_t*)(sWlo + n * WPAD + kk * 16 + 8 + tig * 2);
            mma16816(&acc4[nt * 4], ahi[kk*4], ahi[kk*4+1], ahi[kk*4+2], ahi[kk*4+3], bh0, bh1);
            mma16816(&acc4[nt * 4], ahi[kk*4], ahi[kk*4+1], ahi[kk*4+2], ahi[kk*4+3], bl0, bl1);
            mma16816(&acc4[nt * 4], alo[kk*4], alo[kk*4+1], alo[kk*4+2], alo[kk*4+3], bh0, bh1);
        }
    }
    #pragma unroll
    for (int nt = 0; nt < 8; nt++) {
        int col = nt * 8 + tig * 2;
        if (v0) {
            float2 o; o.x = acc4[nt*4 + 0]; o.y = acc4[nt*4 + 1];
            *(float2*)(out + (size_t)r0 * OUTD + col) = o;
        }
        if (v8) {
            float2 o; o.x = acc4[nt*4 + 2]; o.y = acc4[nt*4 + 3];
            *(float2*)(out + (size_t)r8 * OUTD + col) = o;
        }
    }
}

// ---------------- launch ----------------
extern "C" void kernel_launch(void* const* d_in, const int* in_sizes, int n_in,
                              void* d_out, int out_size) {
    const float* x  = (const float*)d_in[0];
    const void*  ei = d_in[1];
    const float* W1 = (const float*)d_in[2];
    const float* b1 = (const float*)d_in[3];
    const float* W2 = (const float*)d_in[4];
    const float* b2 = (const float*)d_in[5];
    const float* W3 = (const float*)d_in[6];
    const float* b3 = (const float*)d_in[7];
    const float* W4 = (const float*)d_in[8];
    const float* b4 = (const float*)d_in[9];
    float* out = (float*)d_out;

    const int NB_SCAN = (NN + 1023) / 1024;  // 98

    zero_deg_kernel<<<(NN + 255) / 256, 256>>>();
    detect_kernel<<<1, 32>>>((const unsigned int*)ei);
    hist_kernel<<<(NE + 255) / 256, 256>>>(ei);
    scan_block_kernel<<<NB_SCAN, 1024>>>();
    scan_top_kernel<<<1, 32>>>(NB_SCAN);
    scan_add_kernel<<<(NN + 255) / 256, 256>>>();
    place_kernel<<<(NE + 255) / 256, 256>>>(ei);
    wprep_kernel<<<(57344 + 255) / 256, 256>>>(W1, W2, W3, W4);
    gather_kernel<<<(NN + 7) / 8, 256>>>(x);

    cudaFuncSetAttribute(mlp_kernel, cudaFuncAttributeMaxDynamicSharedMemorySize, SM_TOTAL);
    mlp_kernel<<<(NN + 127) / 128, 256, SM_TOTAL>>>(x, b1, b2, b3, b4, out);
}

// round 4
// speedup vs baseline: 1.9547x; 1.6685x over previous
#include <cuda_runtime.h>
#include <cuda_bf16.h>
#include <cstdint>

#define NN   100000
#define NE   1250000
#define IND  64
#define HID  128
#define OUTD 64

// ---------------- device scratch (no cudaMalloc allowed) ----------------
__device__ __align__(16) float g_agg[NN * IND];   // normalized mean-agg, 25.6 MB
__device__ int g_degi[NN];
__device__ int g_off[NN + 1];
__device__ int g_cursor[NN];
__device__ int g_bsum[128];
__device__ int g_ecol[NE];
__device__ __align__(16) __nv_bfloat16 g_Whi[57344];  // W1..W4 transposed [n][k], bf16 hi
__device__ __align__(16) __nv_bfloat16 g_Wlo[57344];  // bf16 residual
__device__ int g_is64;

// ---------------- helpers ----------------
__device__ __forceinline__ void mma16816(float* c,
        uint32_t a0, uint32_t a1, uint32_t a2, uint32_t a3,
        uint32_t b0, uint32_t b1) {
    asm volatile(
        "mma.sync.aligned.m16n8k16.row.col.f32.bf16.bf16.f32 "
        "{%0,%1,%2,%3}, {%4,%5,%6,%7}, {%8,%9}, {%0,%1,%2,%3};"
        : "+f"(c[0]), "+f"(c[1]), "+f"(c[2]), "+f"(c[3])
        : "r"(a0), "r"(a1), "r"(a2), "r"(a3), "r"(b0), "r"(b1));
}

__device__ __forceinline__ void ldsm4(uint32_t addr, uint32_t* r) {
    asm volatile("ldmatrix.sync.aligned.m8n8.x4.shared.b16 {%0,%1,%2,%3}, [%4];"
                 : "=r"(r[0]), "=r"(r[1]), "=r"(r[2]), "=r"(r[3]) : "r"(addr));
}

__device__ __forceinline__ uint32_t smem_u32(const void* p) {
    uint32_t a;
    asm("{ .reg .u64 t; cvta.to.shared.u64 t, %1; cvt.u32.u64 %0, t; }" : "=r"(a) : "l"(p));
    return a;
}

__device__ __forceinline__ void split2(float x0, float x1, uint32_t& hi, uint32_t& lo) {
    __nv_bfloat162 h = __floats2bfloat162_rn(x0, x1);
    float r0 = x0 - __bfloat162float(h.x);
    float r1 = x1 - __bfloat162float(h.y);
    __nv_bfloat162 l = __floats2bfloat162_rn(r0, r1);
    hi = *reinterpret_cast<uint32_t*>(&h);
    lo = *reinterpret_cast<uint32_t*>(&l);
}

__device__ __forceinline__ void load_edge(const void* ei_raw, long long e, int& r, int& c) {
    if (g_is64) {
        const long long* ei = (const long long*)ei_raw;
        r = (int)ei[e]; c = (int)ei[NE + e];
    } else {
        const int* ei = (const int*)ei_raw;
        r = ei[e]; c = ei[NE + e];
    }
}

// ---------------- CSR build ----------------
__global__ void zero_deg_kernel() {
    int i = blockIdx.x * blockDim.x + threadIdx.x;
    if (i < NN) g_degi[i] = 0;
}

__global__ void detect_kernel(const unsigned int* words) {
    if (threadIdx.x == 0 && blockIdx.x == 0) {
        int is64 = 1;
        for (int t = 0; t < 256; t++)
            if (words[2 * t + 1] != 0u) { is64 = 0; break; }
        g_is64 = is64;
    }
}

__global__ void hist_kernel(const void* ei_raw) {
    long long e = (long long)blockIdx.x * 256 + threadIdx.x;
    if (e >= NE) return;
    int r, c;
    load_edge(ei_raw, e, r, c);
    asm volatile("red.global.add.u32 [%0], %1;" :: "l"(g_degi + r), "r"(1) : "memory");
}

__global__ void scan_block_kernel() {
    __shared__ int s[1024];
    int tid = threadIdx.x;
    int i = blockIdx.x * 1024 + tid;
    int val = (i < NN) ? g_degi[i] : 0;
    s[tid] = val;
    __syncthreads();
    #pragma unroll
    for (int d = 1; d < 1024; d <<= 1) {
        int t = (tid >= d) ? s[tid - d] : 0;
        __syncthreads();
        s[tid] += t;
        __syncthreads();
    }
    if (i < NN) g_off[i] = s[tid] - val;
    if (tid == 1023) g_bsum[blockIdx.x] = s[1023];
}

__global__ void scan_top_kernel(int nblocks) {
    if (threadIdx.x == 0) {
        int run = 0;
        for (int b = 0; b < nblocks; b++) { int t = g_bsum[b]; g_bsum[b] = run; run += t; }
    }
}

__global__ void scan_add_kernel() {
    int i = blockIdx.x * blockDim.x + threadIdx.x;
    if (i < NN) {
        int off = g_off[i] + g_bsum[i >> 10];
        g_off[i] = off;
        g_cursor[i] = off;
    }
    if (i == 0) g_off[NN] = NE;
}

__global__ void place_kernel(const void* ei_raw) {
    long long e = (long long)blockIdx.x * 256 + threadIdx.x;
    if (e >= NE) return;
    int r, c;
    load_edge(ei_raw, e, r, c);
    int pos = atomicAdd(&g_cursor[r], 1);
    g_ecol[pos] = c;
}

// ---------------- gather-sum (no float atomics) ----------------
__global__ void __launch_bounds__(256)
gather_kernel(const float* __restrict__ x) {
    int node = blockIdx.x * 8 + (threadIdx.x >> 5);
    if (node >= NN) return;
    int lane = threadIdx.x & 31;
    int off0 = g_off[node], off1 = g_off[node + 1];
    int deg = off1 - off0;
    float ax = 0.f, ay = 0.f;
    for (int i = 0; i < deg; i += 32) {
        int col_l = (i + lane < deg) ? g_ecol[off0 + i + lane] : 0;
        int cnt = min(32, deg - i);
        for (int j = 0; j < cnt; j++) {
            int cc = __shfl_sync(0xFFFFFFFFu, col_l, j);
            float2 v = *(const float2*)(x + (size_t)cc * IND + lane * 2);
            ax += v.x; ay += v.y;
        }
    }
    float inv = 1.0f / fmaxf((float)deg, 1.0f);
    float2 o; o.x = ax * inv; o.y = ay * inv;
    *(float2*)(g_agg + (size_t)node * IND + lane * 2) = o;
}

// ---------------- weight transpose + bf16 hi/lo split -------------
__global__ void wprep_kernel(const float* __restrict__ W1, const float* __restrict__ W2,
                             const float* __restrict__ W3, const float* __restrict__ W4) {
    int idx = blockIdx.x * 256 + threadIdx.x;
    if (idx >= 57344) return;
    float v;
    if (idx < 16384)       { int j = idx;         int n = j >> 7, k = j & 127; v = W1[k * HID + n]; }
    else if (idx < 32768)  { int j = idx - 16384; int n = j >> 7, k = j & 127; v = W2[k * HID + n]; }
    else if (idx < 49152)  { int j = idx - 32768; int n = j >> 7, k = j & 127; v = W3[k * HID + n]; }
    else                   { int j = idx - 49152; int n = j >> 7, k = j & 127; v = W4[k * OUTD + n]; }
    __nv_bfloat16 hi = __float2bfloat16(v);
    g_Whi[idx] = hi;
    g_Wlo[idx] = __float2bfloat16(v - __bfloat162float(hi));
}

// ---------------- persistent fused 4-layer MLP ------------------------------
// All 4 layers' weights resident in smem (hi+lo, XOR-swizzled, stride 256B).
// 152 persistent CTAs, 8 warps each; warps fully independent after one sync.
// smem: 448 rows x 256B (hi) + 448 x 256B (lo) + 448 f32 bias = 231168 B.
#define SM_LO_OFF   114688
#define SM_BIAS_OFF 229376
#define SM_TOTAL    231168
#define NWARPS_TOT  (152 * 8)
#define NCHUNK      6250            // 100000 / 16

__global__ void __launch_bounds__(256, 1)
mlp_kernel(const float* __restrict__ x,
           const float* __restrict__ b1, const float* __restrict__ b2,
           const float* __restrict__ b3, const float* __restrict__ b4,
           float* __restrict__ out) {
    extern __shared__ char sm[];
    float* sbias = (float*)(sm + SM_BIAS_OFF);
    uint32_t sw = smem_u32(sm);

    int tid = threadIdx.x;
    int wid = tid >> 5, lane = tid & 31;
    int gid = lane >> 2, tig = lane & 3;

    // ---- stage all weights once (hi then lo), XOR-swizzled ----
    for (int i = tid; i < 14336; i += 256) {
        int half = i >= 7168;
        int j = half ? i - 7168 : i;
        int row = j >> 4, g = j & 15;
        uint4 v = *(const uint4*)((half ? g_Wlo : g_Whi) + row * 128 + g * 8);
        uint32_t dst = (half ? SM_LO_OFF : 0) + (row << 8) + (((uint32_t)g << 4) ^ (((uint32_t)(row & 7)) << 4));
        *(uint4*)(sm + dst) = v;
    }
    for (int i = tid; i < 448; i += 256) {
        float b;
        if (i < 128)      b = b1[i];
        else if (i < 256) b = b2[i - 128];
        else if (i < 384) b = b3[i - 256];
        else              b = b4[i - 384];
        sbias[i] = b;
    }
    __syncthreads();

    // per-lane ldmatrix address components
    int row_part = (lane & 7) + ((lane >> 4) << 3);       // row within 16-row pair block
    uint32_t kxor = ((uint32_t)(lane & 7)) << 4;
    uint32_t kbh  = ((uint32_t)((lane >> 3) & 1)) << 4;   // matrix 0/1 -> k half
    uint32_t lanebase_hi = sw + ((uint32_t)row_part << 8);
    uint32_t lanebase_lo = lanebase_hi + SM_LO_OFF;

    int gw = blockIdx.x * 8 + wid;
    for (int chunk = gw; chunk < NCHUNK; chunk += NWARPS_TOT) {
        int r0 = chunk * 16 + gid;
        int r8 = r0 + 8;

        uint32_t ahi[32], alo[32];
        // ---- build layer-1 A fragments from x | agg (pre-normalized) ----
        #pragma unroll
        for (int kk = 0; kk < 8; kk++) {
            #pragma unroll
            for (int h = 0; h < 4; h++) {
                int rr = (h & 1) ? r8 : r0;
                int c = kk * 16 + ((h & 2) ? 8 : 0) + tig * 2;
                const float* src = (c < 64) ? (x + (size_t)rr * IND + c)
                                            : (g_agg + (size_t)rr * IND + (c - 64));
                float2 t = *(const float2*)src;
                split2(t.x, t.y, ahi[kk * 4 + h], alo[kk * 4 + h]);
            }
        }

        // ---- layers 1..4 ----
        #pragma unroll
        for (int l = 0; l < 4; l++) {
            int lrow = l * 128;
            int nq = (l == 3) ? 2 : 4;          // groups of 4 n-tiles (n32)
            float acc[64];
            #pragma unroll
            for (int nt = 0; nt < 16; nt++) {
                if (nt < nq * 4) {
                    float2 bb = *(const float2*)(sbias + lrow + nt * 8 + tig * 2);
                    acc[nt * 4 + 0] = bb.x; acc[nt * 4 + 1] = bb.y;
                    acc[nt * 4 + 2] = bb.x; acc[nt * 4 + 3] = bb.y;
                }
            }
            #pragma unroll
            for (int kk = 0; kk < 8; kk++) {
                uint32_t kpart = (((uint32_t)kk << 5) + kbh) ^ kxor;
                #pragma unroll 4
                for (int ntq = 0; ntq < nq; ntq++) {
                    uint32_t rowoff = ((uint32_t)(lrow + ntq * 32) << 8);
                    uint32_t h[8], lg[8];
                    ldsm4(lanebase_hi + rowoff + kpart,               h);
                    ldsm4(lanebase_hi + rowoff + (16u << 8) + kpart,  h + 4);
                    ldsm4(lanebase_lo + rowoff + kpart,               lg);
                    ldsm4(lanebase_lo + rowoff + (16u << 8) + kpart,  lg + 4);
                    uint32_t* ah = &ahi[kk * 4];
                    uint32_t* al = &alo[kk * 4];
                    #pragma unroll
                    for (int s = 0; s < 4; s++)
                        mma16816(&acc[(ntq * 4 + s) * 4], ah[0], ah[1], ah[2], ah[3], h[s*2], h[s*2+1]);
                    #pragma unroll
                    for (int s = 0; s < 4; s++)
                        mma16816(&acc[(ntq * 4 + s) * 4], ah[0], ah[1], ah[2], ah[3], lg[s*2], lg[s*2+1]);
                    #pragma unroll
                    for (int s = 0; s < 4; s++)
                        mma16816(&acc[(ntq * 4 + s) * 4], al[0], al[1], al[2], al[3], h[s*2], h[s*2+1]);
                }
            }
            if (l < 3) {
                // ReLU + re-split into next layer's A fragments
                #pragma unroll
                for (int kk = 0; kk < 8; kk++) {
                    #pragma unroll
                    for (int h = 0; h < 4; h++) {
                        float p0 = fmaxf(acc[8*kk + 2*h + 0], 0.f);
                        float p1 = fmaxf(acc[8*kk + 2*h + 1], 0.f);
                        split2(p0, p1, ahi[4*kk + h], alo[4*kk + h]);
                    }
                }
            } else {
                #pragma unroll
                for (int nt = 0; nt < 8; nt++) {
                    int col = nt * 8 + tig * 2;
                    float2 o0; o0.x = acc[nt*4 + 0]; o0.y = acc[nt*4 + 1];
                    *(float2*)(out + (size_t)r0 * OUTD + col) = o0;
                    float2 o1; o1.x = acc[nt*4 + 2]; o1.y = acc[nt*4 + 3];
                    *(float2*)(out + (size_t)r8 * OUTD + col) = o1;
                }
            }
        }
    }
}

// ---------------- launch ----------------
extern "C" void kernel_launch(void* const* d_in, const int* in_sizes, int n_in,
                              void* d_out, int out_size) {
    const float* x  = (const float*)d_in[0];
    const void*  ei = d_in[1];
    const float* W1 = (const float*)d_in[2];
    const float* b1 = (const float*)d_in[3];
    const float* W2 = (const float*)d_in[4];
    const float* b2 = (const float*)d_in[5];
    const float* W3 = (const float*)d_in[6];
    const float* b3 = (const float*)d_in[7];
    const float* W4 = (const float*)d_in[8];
    const float* b4 = (const float*)d_in[9];
    float* out = (float*)d_out;

    const int NB_SCAN = (NN + 1023) / 1024;

    zero_deg_kernel<<<(NN + 255) / 256, 256>>>();
    detect_kernel<<<1, 32>>>((const unsigned int*)ei);
    hist_kernel<<<(NE + 255) / 256, 256>>>(ei);
    scan_block_kernel<<<NB_SCAN, 1024>>>();
    scan_top_kernel<<<1, 32>>>(NB_SCAN);
    scan_add_kernel<<<(NN + 255) / 256, 256>>>();
    place_kernel<<<(NE + 255) / 256, 256>>>(ei);
    wprep_kernel<<<(57344 + 255) / 256, 256>>>(W1, W2, W3, W4);
    gather_kernel<<<(NN + 7) / 8, 256>>>(x);

    cudaFuncSetAttribute(mlp_kernel, cudaFuncAttributeMaxDynamicSharedMemorySize, SM_TOTAL);
    mlp_kernel<<<152, 256, SM_TOTAL>>>(x, b1, b2, b3, b4, out);
}